// round 6
// baseline (speedup 1.0000x reference)
#include <cuda_runtime.h>
#include <cstdint>

#define NTAGS 48
#define SEQ 512
#define BSZ 64
#define NTRANS (NTAGS*NTAGS)         // 2304 floats per gmem tile
#define ROWSTRIDE 52                 // padded smem row stride: conflict-free
#define TILE_PAD (NTAGS*ROWSTRIDE)
#define STAGES 4
#define NTHREADS 384
#define CHUNKS (NTAGS*12)            // 576 x 16B per tile
#define LOG2E_F 1.4426950408889634f
#define LN2_F   0.6931471805599453f
#define START_TAG 46
#define END_TAG 47
#define MARGIN 24.0f

__device__ float g_part[BSZ];

__device__ __forceinline__ float ex2f(float x){
    float y; asm("ex2.approx.ftz.f32 %0, %1;" : "=f"(y) : "f"(x)); return y;
}
__device__ __forceinline__ float lg2f(float x){
    float y; asm("lg2.approx.ftz.f32 %0, %1;" : "=f"(y) : "f"(x)); return y;
}
__device__ __forceinline__ void cp16(uint32_t s, const void* g){
    asm volatile("cp.async.cg.shared.global [%0], [%1], 16;" :: "r"(s), "l"(g));
}
__device__ __forceinline__ void cp_commit(){ asm volatile("cp.async.commit_group;"); }
__device__ __forceinline__ void cp_wait1(){ asm volatile("cp.async.wait_group 1;"); }
__device__ __forceinline__ void cp_wait2(){ asm volatile("cp.async.wait_group 2;"); }

__global__ __launch_bounds__(NTHREADS, 1)
void crf_fwd_kernel(const float* __restrict__ tr,
                    const int* __restrict__ tgt)
{
    __shared__ __align__(16) float buf[STAGES][TILE_PAD];  // 39936 B
    __shared__ float vbuf[2][NTAGS];    // v = exp(fw - C), double buffered
    __shared__ float Mbuf[2];           // C for the *producer* side, per parity
    __shared__ float fwend;             // forw[END] at final step
    __shared__ unsigned char tg[SEQ];

    const int tid = threadIdx.x;
    const int b   = blockIdx.x;
    const float* trb = tr + (size_t)b * SEQ * NTRANS;

    for (int i = tid; i < SEQ; i += NTHREADS){
        int v = tgt[(size_t)b * SEQ + i];
        tg[i] = (unsigned char)(((unsigned)v < NTAGS) ? v : 0);
    }

    const int w   = tid >> 5;
    const int l   = tid & 31;
    const int col = (w << 2) + (l & 3);   // column 0..47
    const int q   = l >> 2;               // row subgroup: rows q, q+8, ..., q+40

    const int c0 = tid;
    const int c1 = tid + NTHREADS;
    const int r0a = c0 / 12, o0a = c0 % 12;
    const int r1a = c1 / 12, o1a = c1 % 12;

    auto prefetch = [&](int t){
        uint32_t sb = (uint32_t)__cvta_generic_to_shared(&buf[t & (STAGES-1)][0]);
        const float* gb = trb + (size_t)t * NTRANS;
        cp16(sb + (uint32_t)(r0a * (ROWSTRIDE*4) + o0a * 16), gb + c0 * 4);
        if (c1 < CHUNKS)
            cp16(sb + (uint32_t)(r1a * (ROWSTRIDE*4) + o1a * 16), gb + c1 * 4);
    };

    // prologue: prefetch tiles 0..3 (4 groups)
    prefetch(0); cp_commit();
    prefetch(1); cp_commit();
    prefetch(2); cp_commit();
    prefetch(3); cp_commit();

    cp_wait2();                // tiles 0 and 1 complete
    __syncthreads();

    // ---- t = 0 init ----
    float tscore = 0.f;
    unsigned char prev = tg[0];
    const float C0 = buf[0][START_TAG * ROWSTRIDE + 0] + MARGIN;  // broadcast LDS
    float Creg = C0;           // normalizer baked into vbuf[0]
    if (tid == 0){
        tscore = buf[0][START_TAG * ROWSTRIDE + prev];
        Mbuf[1] = C0;          // C for producers at step 1
        fwend = 0.f;
    }
    if (q == 0){
        float fw0 = buf[0][START_TAG * ROWSTRIDE + col];
        vbuf[0][col] = ex2f((fw0 - C0) * LOG2E_F);
    }
    // Etr for step 1 (tile 1 resident)
    float E0, E1, E2, E3, E4, E5;
    {
        const float* tn = &buf[1][0];
        E0 = ex2f(tn[(q     ) * ROWSTRIDE + col] * LOG2E_F);
        E1 = ex2f(tn[(q +  8) * ROWSTRIDE + col] * LOG2E_F);
        E2 = ex2f(tn[(q + 16) * ROWSTRIDE + col] * LOG2E_F);
        E3 = ex2f(tn[(q + 24) * ROWSTRIDE + col] * LOG2E_F);
        E4 = ex2f(tn[(q + 32) * ROWSTRIDE + col] * LOG2E_F);
        E5 = ex2f(tn[(q + 40) * ROWSTRIDE + col] * LOG2E_F);
    }

    for (int t = 1; t < SEQ; ++t){
        cp_wait1();            // tiles <= t+1 complete
        __syncthreads();       // vbuf[t-1], Mbuf visible; stage (t+3)&3 free

        if (t + 3 < SEQ) prefetch(t + 3);
        cp_commit();           // uniform group count

        const float  Cv = Mbuf[t & 1];            // producer C for this step
        const float* vp = vbuf[(t-1) & 1];

        // ---- critical chain: s_j = sum_r Etr[r][j] * v[r] ----
        float s01 = fmaf(E1, vp[q +  8], E0 * vp[q]);
        float s23 = fmaf(E3, vp[q + 24], E2 * vp[q + 16]);
        float s45 = fmaf(E5, vp[q + 40], E4 * vp[q + 32]);
        float s = (s01 + s23) + s45;
        s += __shfl_xor_sync(0xffffffffu, s, 4);
        s += __shfl_xor_sync(0xffffffffu, s, 8);
        s += __shfl_xor_sync(0xffffffffu, s, 16);

        float fnew = fmaf(lg2f(s), LN2_F, Creg);  // forw_t[col] on every lane

        if (q == 0)
            vbuf[t & 1][col] = ex2f((fnew - Cv) * LOG2E_F);

        if (tid == 0){
            Mbuf[(t + 1) & 1] = fnew + MARGIN;    // fnew here = forw_t[0]
            unsigned char cur = tg[t];
            tscore += buf[t & (STAGES-1)][(int)prev * ROWSTRIDE + cur];
            prev = cur;
        }
        if (t == SEQ - 1 && q == 0 && col == END_TAG)
            fwend = fnew;

        Creg = Cv;             // next step reconstructs with this normalizer

        // ---- off-path: Etr for step t+1 from tile t+1 ----
        if (t < SEQ - 1){
            const float* tn = &buf[(t+1) & (STAGES-1)][0];
            E0 = ex2f(tn[(q     ) * ROWSTRIDE + col] * LOG2E_F);
            E1 = ex2f(tn[(q +  8) * ROWSTRIDE + col] * LOG2E_F);
            E2 = ex2f(tn[(q + 16) * ROWSTRIDE + col] * LOG2E_F);
            E3 = ex2f(tn[(q + 24) * ROWSTRIDE + col] * LOG2E_F);
            E4 = ex2f(tn[(q + 32) * ROWSTRIDE + col] * LOG2E_F);
            E5 = ex2f(tn[(q + 40) * ROWSTRIDE + col] * LOG2E_F);
        }
    }

    __syncthreads();
    if (tid == 0)
        g_part[b] = fwend - tscore;
}

__global__ void finalize_kernel(float* o){
    int t = threadIdx.x;                      // 32 threads
    double v = (double)g_part[t] + (double)g_part[t + 32];
    #pragma unroll
    for (int m = 16; m > 0; m >>= 1)
        v += __shfl_xor_sync(0xffffffffu, v, m);
    if (t == 0) *o = (float)(v * (1.0 / (double)BSZ));
}

extern "C" void kernel_launch(void* const* d_in, const int* in_sizes, int n_in,
                              void* d_out, int out_size)
{
    const float* tr  = (const float*)d_in[0];
    const int*   tgt = (const int*)d_in[1];
    float*       out = (float*)d_out;

    crf_fwd_kernel<<<BSZ, NTHREADS>>>(tr, tgt);
    finalize_kernel<<<1, 32>>>(out);
}

// round 7
// speedup vs baseline: 1.1883x; 1.1883x over previous
#include <cuda_runtime.h>
#include <cstdint>

#define NTAGS 48
#define SEQ 512
#define BSZ 64
#define NTRANS (NTAGS*NTAGS)         // 2304 floats per gmem tile
#define RST 50                        // smem row stride (floats)
#define TILE_PAD (NTAGS*RST)          // 2400 floats = 9600 B per stage
#define STAGES 5
#define NTHREADS 384
#define LOG2E_F 1.4426950408889634f
#define LN2_D   0.6931471805599453
#define START_TAG 46
#define END_TAG 47

__device__ float g_part[BSZ];

__device__ __forceinline__ float ex2f(float x){
    float y; asm("ex2.approx.ftz.f32 %0, %1;" : "=f"(y) : "f"(x)); return y;
}
__device__ __forceinline__ float lg2f(float x){
    float y; asm("lg2.approx.ftz.f32 %0, %1;" : "=f"(y) : "f"(x)); return y;
}
__device__ __forceinline__ void cp8(uint32_t s, const void* g){
    asm volatile("cp.async.ca.shared.global [%0], [%1], 8;" :: "r"(s), "l"(g));
}
__device__ __forceinline__ void cp_commit(){ asm volatile("cp.async.commit_group;"); }
__device__ __forceinline__ void cp_wait2(){ asm volatile("cp.async.wait_group 2;"); }
__device__ __forceinline__ void cp_wait3(){ asm volatile("cp.async.wait_group 3;"); }

__global__ __launch_bounds__(NTHREADS, 1)
void crf_fwd_kernel(const float* __restrict__ tr,
                    const int* __restrict__ tgt)
{
    __shared__ __align__(16) float buf[STAGES][TILE_PAD];  // 48000 B
    __shared__ __align__(16) float vbuf[2][NTAGS];         // 384 B
    __shared__ float scalebuf[2];
    __shared__ float tsc_sh;
    __shared__ unsigned char tg[SEQ];                      // 512 B

    const int tid = threadIdx.x;
    const int b   = blockIdx.x;
    const float* trb = tr + (size_t)b * SEQ * NTRANS;

    for (int i = tid; i < SEQ; i += NTHREADS){
        int v = tgt[(size_t)b * SEQ + i];
        tg[i] = (unsigned char)(((unsigned)v < NTAGS) ? v : 0);
    }

    const int w   = tid >> 5;
    const int l   = tid & 31;
    const int col = (w << 2) + (l & 3);   // column 0..47
    const int q   = l >> 2;               // 0..7 -> rows 6q..6q+5

    // 8B cp.async chunk coords (3 chunks/thread, 1152 per tile)
    const int cA = tid, cB = tid + NTHREADS, cC = tid + 2*NTHREADS;
    const uint32_t smA = (uint32_t)((cA/24)*(RST*4) + (cA%24)*8);
    const uint32_t smB = (uint32_t)((cB/24)*(RST*4) + (cB%24)*8);
    const uint32_t smC = (uint32_t)((cC/24)*(RST*4) + (cC%24)*8);
    const int gmA = (cA/24)*NTAGS + (cA%24)*2;
    const int gmB = (cB/24)*NTAGS + (cB%24)*2;
    const int gmC = (cC/24)*NTAGS + (cC%24)*2;
    const uint32_t sbase = (uint32_t)__cvta_generic_to_shared(&buf[0][0]);

    auto prefetch = [&](int tile_idx, int stg){
        uint32_t sb = sbase + (uint32_t)stg * (TILE_PAD*4);
        const float* gb = trb + (size_t)tile_idx * NTRANS;
        cp8(sb + smA, gb + gmA);
        cp8(sb + smB, gb + gmB);
        cp8(sb + smC, gb + gmC);
    };

    // prologue: tiles 0..4, one commit group each
    prefetch(0,0); cp_commit();
    prefetch(1,1); cp_commit();
    prefetch(2,2); cp_commit();
    prefetch(3,3); cp_commit();
    prefetch(4,4); cp_commit();

    cp_wait3();            // tiles 0,1 complete
    __syncthreads();

    // ---- init (t = 0) ----
    const float* b0 = &buf[0][0];
    const float fw00 = b0[START_TAG*RST];                    // broadcast
    const int P0 = __float2int_rn(fw00 * LOG2E_F);
    float v0 = ex2f(fmaf(b0[START_TAG*RST + col], LOG2E_F, (float)(-P0)));
    if (q == 0) vbuf[0][col] = v0;

    float tscore = 0.f;    // tid 383
    int   prev   = tg[0];
    int   Ksum = 0, kcur = 0;   // tid 4
    if (tid == NTHREADS-1) tscore = b0[START_TAG*RST + prev];
    if (tid == 4){
        // v0 on tid4 is col 0 (w=0, l&3=0)
        int e = (__float_as_int(v0) >> 23) & 255;
        kcur = e - 127;
        scalebuf[1] = __int_as_float((127 - kcur) << 23);
    }

    // Etr for step 1 from tile 1
    const int r0 = q * 6;
    float E0,E1,E2,E3,E4,E5;
    {
        const float* tn = &buf[1][0];
        E0 = ex2f(tn[(r0  )*RST + col] * LOG2E_F);
        E1 = ex2f(tn[(r0+1)*RST + col] * LOG2E_F);
        E2 = ex2f(tn[(r0+2)*RST + col] * LOG2E_F);
        E3 = ex2f(tn[(r0+3)*RST + col] * LOG2E_F);
        E4 = ex2f(tn[(r0+4)*RST + col] * LOG2E_F);
        E5 = ex2f(tn[(r0+5)*RST + col] * LOG2E_F);
    }

    int st = 1;                                  // stage holding tile t
    for (int t = 1; t < SEQ; ++t){
        cp_wait2();        // tiles <= t+1 complete
        __syncthreads();   // vbuf/scalebuf of t-1 visible; stage (t-1)%5 free

        const int stp = (st == 0) ? 4 : st - 1;  // = (t+4) % 5
        const int stn = (st == 4) ? 0 : st + 1;  // = (t+1) % 5
        if (t + 4 < SEQ) prefetch(t + 4, stp);
        cp_commit();                              // uniform group count

        // ---- loads first (MLP), then off-path ex2 for t+1, then the chain ----
        const float  sc = scalebuf[t & 1];
        const float* vp = &vbuf[(t-1) & 1][0];
        const float2* vp2 = (const float2*)vp;    // r0 = 6q is even
        float2 va = vp2[3*q], vb2 = vp2[3*q+1], vc = vp2[3*q+2];

        float F0,F1,F2,F3,F4,F5;                  // Etr for step t+1 (unused at t=SEQ-1)
        {
            const float* tn = &buf[stn][0];
            F0 = ex2f(tn[(r0  )*RST + col] * LOG2E_F);
            F1 = ex2f(tn[(r0+1)*RST + col] * LOG2E_F);
            F2 = ex2f(tn[(r0+2)*RST + col] * LOG2E_F);
            F3 = ex2f(tn[(r0+3)*RST + col] * LOG2E_F);
            F4 = ex2f(tn[(r0+4)*RST + col] * LOG2E_F);
            F5 = ex2f(tn[(r0+5)*RST + col] * LOG2E_F);
        }

        // ---- critical chain (E regs from previous iter: no wait) ----
        float s01 = fmaf(E1, va.y, E0 * va.x);
        float s23 = fmaf(E3, vb2.y, E2 * vb2.x);
        float s45 = fmaf(E5, vc.y, E4 * vc.x);
        float s = (s01 + s23) + s45;
        s += __shfl_xor_sync(0xffffffffu, s, 4);
        s += __shfl_xor_sync(0xffffffffu, s, 8);
        s += __shfl_xor_sync(0xffffffffu, s, 16);
        float v = s * sc;
        if (q == 0) vbuf[t & 1][col] = v;

        // ---- off-path bookkeeping ----
        if (tid == 4){
            Ksum += kcur;                         // scale applied this step
            float w0 = vp[0];                     // v_{t-1}[0]: 2-step-stale scale source
            int e = (__float_as_int(w0) >> 23) & 255;
            kcur = e - 127;
            scalebuf[(t+1) & 1] = __int_as_float((127 - kcur) << 23);
        }
        if (tid == NTHREADS-1){
            int cur = tg[t];
            tscore += buf[st][prev*RST + cur];
            prev = cur;
        }

        E0=F0; E1=F1; E2=F2; E3=F3; E4=F4; E5=F5;
        st = stn;
    }

    if (tid == NTHREADS-1) tsc_sh = tscore;
    __syncthreads();
    if (tid == 4){
        Ksum += kcur;                             // applied at the final step? no:
        Ksum -= kcur;                             // (kcur written for step SEQ, never applied)
        float vf = vbuf[(SEQ-1) & 1][END_TAG];
        int   eu = ((__float_as_int(vf) >> 23) & 255) - 127;
        float mu = __int_as_float((__float_as_int(vf) & 0x807FFFFF) | 0x3F800000);
        double log2u = (double)(eu + P0 + Ksum) + (double)lg2f(mu);
        g_part[b] = (float)(LN2_D * log2u - (double)tsc_sh);
    }
}

__global__ void finalize_kernel(float* o){
    int t = threadIdx.x;                      // 32 threads
    double v = (double)g_part[t] + (double)g_part[t + 32];
    #pragma unroll
    for (int m = 16; m > 0; m >>= 1)
        v += __shfl_xor_sync(0xffffffffu, v, m);
    if (t == 0) *o = (float)(v * (1.0 / (double)BSZ));
}

extern "C" void kernel_launch(void* const* d_in, const int* in_sizes, int n_in,
                              void* d_out, int out_size)
{
    const float* tr  = (const float*)d_in[0];
    const int*   tgt = (const int*)d_in[1];
    float*       out = (float*)d_out;

    crf_fwd_kernel<<<BSZ, NTHREADS>>>(tr, tgt);
    finalize_kernel<<<1, 32>>>(out);
}